// round 9
// baseline (speedup 1.0000x reference)
#include <cuda_runtime.h>

// Problem constants (fixed by the reference)
#define N_LAYERS 12
#define D_SAE    16384
#define D_MODEL  768
#define NNZ      131072

#define VEC      (D_MODEL / 4)   // 192 float4 per row
#define WARPS_PER_BLOCK 8
#define THREADS (WARPS_PER_BLOCK * 32)
#define NUM_SMS  148
#define BLOCKS_PER_SM 8
#define GRID     (NUM_SMS * BLOCKS_PER_SM)          // 1184 blocks = one wave
#define TOTAL_WARPS (GRID * WARPS_PER_BLOCK)        // 9472 warps

__global__ __launch_bounds__(THREADS)
void gather_scale_kernel(const float4* __restrict__ W,      // [N_LAYERS*D_SAE, 192]
                         const float*  __restrict__ vals,   // [NNZ]
                         const int*    __restrict__ lidx,   // [NNZ]
                         const int*    __restrict__ fidx,   // [NNZ]
                         float4*       __restrict__ out)    // [NNZ, 192]
{
    const int warp_in_blk = threadIdx.x >> 5;
    const int lane        = threadIdx.x & 31;
    const int warp_gid    = blockIdx.x * WARPS_PER_BLOCK + warp_in_blk;

    // Persistent grid-stride over nonzeros: one wave of CTAs, each warp loops.
    // Adjacent warps hit adjacent nonzeros each iteration -> layer-segment
    // locality in L2 is preserved; no wave-transition DRAM bubbles.
    for (int nz = warp_gid; nz < NNZ; nz += TOTAL_WARPS) {
        const float v   = __ldg(&vals[nz]);
        const long  row = (long)__ldg(&lidx[nz]) * D_SAE + (long)__ldg(&fidx[nz]);

        const float4* __restrict__ src = W   + row * (long)VEC;
        float4*       __restrict__ dst = out + (long)nz * (long)VEC;

        #pragma unroll
        for (int i = 0; i < VEC / 32; ++i) {
            const int idx = lane + i * 32;
            float4 a = __ldg(&src[idx]);
            a.x *= v; a.y *= v; a.z *= v; a.w *= v;
            __stcs(&dst[idx], a);
        }
    }
}

extern "C" void kernel_launch(void* const* d_in, const int* in_sizes, int n_in,
                              void* d_out, int out_size)
{
    // metadata order: W_D (f32), values (f32), layer_idx (i32), pos_idx (i32), feat_idx (i32)
    const float4* W    = (const float4*)d_in[0];
    const float*  vals = (const float*)d_in[1];
    const int*    lidx = (const int*)d_in[2];
    // pos_idx (d_in[3]) is unused by the reference computation
    const int*    fidx = (const int*)d_in[4];
    float4*       out  = (float4*)d_out;

    gather_scale_kernel<<<GRID, THREADS>>>(W, vals, lidx, fidx, out);
}

// round 11
// speedup vs baseline: 1.1115x; 1.1115x over previous
#include <cuda_runtime.h>

// Problem constants (fixed by the reference)
#define N_LAYERS 12
#define D_SAE    16384
#define D_MODEL  768
#define NNZ      131072

#define VEC      (D_MODEL / 4)   // 192 float4 per row
#define WARPS_PER_BLOCK 8
#define THREADS (WARPS_PER_BLOCK * 32)

__global__ __launch_bounds__(THREADS)
void gather_scale_kernel(const float4* __restrict__ W,      // [N_LAYERS*D_SAE, 192]
                         const float*  __restrict__ vals,   // [NNZ]
                         const int*    __restrict__ lidx,   // [NNZ]
                         const int*    __restrict__ fidx,   // [NNZ]
                         float4*       __restrict__ out)    // [NNZ, 192]
{
    const int warp_in_blk = threadIdx.x >> 5;
    const int lane        = threadIdx.x & 31;
    const int nz          = blockIdx.x * WARPS_PER_BLOCK + warp_in_blk;
    if (nz >= NNZ) return;

    const float v = __ldg(&vals[nz]);
    const long  row = (long)__ldg(&lidx[nz]) * D_SAE + (long)__ldg(&fidx[nz]);

    const float4* __restrict__ src = W   + row * (long)VEC;
    float4*       __restrict__ dst = out + (long)nz * (long)VEC;

    // 192 float4 per row, 32 lanes -> 6 per lane, fully unrolled for MLP.
    // Loads: __ldcg (L2-cached, L1-bypass) — gathered rows have no intra-SM
    //        reuse, so skip the L1 fill; duplicate rows are served by L2.
    // Stores: __stcs (evict-first) — 403MB output stream never re-read.
    #pragma unroll
    for (int i = 0; i < VEC / 32; ++i) {
        const int idx = lane + i * 32;
        float4 a = __ldcg(&src[idx]);
        a.x *= v; a.y *= v; a.z *= v; a.w *= v;
        __stcs(&dst[idx], a);
    }
}

extern "C" void kernel_launch(void* const* d_in, const int* in_sizes, int n_in,
                              void* d_out, int out_size)
{
    // metadata order: W_D (f32), values (f32), layer_idx (i32), pos_idx (i32), feat_idx (i32)
    const float4* W    = (const float4*)d_in[0];
    const float*  vals = (const float*)d_in[1];
    const int*    lidx = (const int*)d_in[2];
    // pos_idx (d_in[3]) is unused by the reference computation
    const int*    fidx = (const int*)d_in[4];
    float4*       out  = (float4*)d_out;

    const int grid = NNZ / WARPS_PER_BLOCK;   // 16384 blocks
    gather_scale_kernel<<<grid, THREADS>>>(W, vals, lidx, fidx, out);
}

// round 12
// speedup vs baseline: 1.2021x; 1.0815x over previous
#include <cuda_runtime.h>

// Problem constants (fixed by the reference)
#define N_LAYERS 12
#define D_SAE    16384
#define D_MODEL  768
#define NNZ      131072

#define VEC      (D_MODEL / 4)   // 192 float4 per row
#define WARPS_PER_BLOCK 8
#define THREADS (WARPS_PER_BLOCK * 32)

__global__ __launch_bounds__(THREADS)
void gather_scale_kernel(const float4* __restrict__ W,      // [N_LAYERS*D_SAE, 192]
                         const float*  __restrict__ vals,   // [NNZ]
                         const int*    __restrict__ lidx,   // [NNZ]
                         const int*    __restrict__ fidx,   // [NNZ]
                         float4*       __restrict__ out)    // [NNZ, 192]
{
    const int warp_in_blk = threadIdx.x >> 5;
    const int lane        = threadIdx.x & 31;
    const int nz          = blockIdx.x * WARPS_PER_BLOCK + warp_in_blk;
    if (nz >= NNZ) return;

    const float v = __ldg(&vals[nz]);
    const long  row = (long)__ldg(&lidx[nz]) * D_SAE + (long)__ldg(&fidx[nz]);

    const float4* __restrict__ src = W   + row * (long)VEC;
    float4*       __restrict__ dst = out + (long)nz * (long)VEC;

    // Explicit front-batch: issue ALL 6 independent LDG.E.128 into distinct
    // registers before any store (guarantees MLP=6 per warp — the single
    // determinant of DRAM utilization for this kernel; R11 showed ptxas can
    // silently serialize these if given the chance).
    float4 a[VEC / 32];
    #pragma unroll
    for (int i = 0; i < VEC / 32; ++i)
        a[i] = __ldg(&src[lane + i * 32]);

    // Scale + evict-first stores (output stream is never re-read).
    #pragma unroll
    for (int i = 0; i < VEC / 32; ++i) {
        a[i].x *= v; a[i].y *= v; a[i].z *= v; a[i].w *= v;
        __stcs(&dst[lane + i * 32], a[i]);
    }
}

extern "C" void kernel_launch(void* const* d_in, const int* in_sizes, int n_in,
                              void* d_out, int out_size)
{
    // metadata order: W_D (f32), values (f32), layer_idx (i32), pos_idx (i32), feat_idx (i32)
    const float4* W    = (const float4*)d_in[0];
    const float*  vals = (const float*)d_in[1];
    const int*    lidx = (const int*)d_in[2];
    // pos_idx (d_in[3]) is unused by the reference computation
    const int*    fidx = (const int*)d_in[4];
    float4*       out  = (float4*)d_out;

    const int grid = NNZ / WARPS_PER_BLOCK;   // 16384 blocks
    gather_scale_kernel<<<grid, THREADS>>>(W, vals, lidx, fidx, out);
}

// round 13
// speedup vs baseline: 1.2086x; 1.0054x over previous
#include <cuda_runtime.h>

// Problem constants (fixed by the reference)
#define N_LAYERS 12
#define D_SAE    16384
#define D_MODEL  768
#define NNZ      131072

#define VEC      (D_MODEL / 4)   // 192 float4 per row
#define WARPS_PER_BLOCK 8
#define THREADS (WARPS_PER_BLOCK * 32)
#define ROWS_PER_WARP 2

// min-blocks=4 -> up to 64 regs/thread: room for a genuine 12x float4
// front-batch (48 regs) without ptxas collapsing it back to 6 live regs
// (which is what silently happened in the earlier 2-row attempt).
__global__ __launch_bounds__(THREADS, 4)
void gather_scale_kernel(const float4* __restrict__ W,      // [N_LAYERS*D_SAE, 192]
                         const float*  __restrict__ vals,   // [NNZ]
                         const int*    __restrict__ lidx,   // [NNZ]
                         const int*    __restrict__ fidx,   // [NNZ]
                         float4*       __restrict__ out)    // [NNZ, 192]
{
    const int warp_in_blk = threadIdx.x >> 5;
    const int lane        = threadIdx.x & 31;
    const int warp_id     = blockIdx.x * WARPS_PER_BLOCK + warp_in_blk;
    const int nz0         = warp_id * ROWS_PER_WARP;
    if (nz0 >= NNZ) return;
    const int nz1 = nz0 + 1;

    const float v0 = __ldg(&vals[nz0]);
    const float v1 = __ldg(&vals[nz1]);
    const long  row0 = (long)__ldg(&lidx[nz0]) * D_SAE + (long)__ldg(&fidx[nz0]);
    const long  row1 = (long)__ldg(&lidx[nz1]) * D_SAE + (long)__ldg(&fidx[nz1]);

    const float4* __restrict__ src0 = W   + row0 * (long)VEC;
    const float4* __restrict__ src1 = W   + row1 * (long)VEC;
    float4*       __restrict__ dst0 = out + (long)nz0 * (long)VEC;
    float4*       __restrict__ dst1 = out + (long)nz1 * (long)VEC;

    // Front-batch all 12 independent LDG.E.128 (2 rows x 6/lane) into
    // distinct registers: true per-warp read MLP = 12.
    float4 a[VEC / 32], b[VEC / 32];
    #pragma unroll
    for (int i = 0; i < VEC / 32; ++i) a[i] = __ldg(&src0[lane + i * 32]);
    #pragma unroll
    for (int i = 0; i < VEC / 32; ++i) b[i] = __ldg(&src1[lane + i * 32]);

    // Scale + evict-first stores.
    #pragma unroll
    for (int i = 0; i < VEC / 32; ++i) {
        a[i].x *= v0; a[i].y *= v0; a[i].z *= v0; a[i].w *= v0;
        __stcs(&dst0[lane + i * 32], a[i]);
    }
    #pragma unroll
    for (int i = 0; i < VEC / 32; ++i) {
        b[i].x *= v1; b[i].y *= v1; b[i].z *= v1; b[i].w *= v1;
        __stcs(&dst1[lane + i * 32], b[i]);
    }
}

extern "C" void kernel_launch(void* const* d_in, const int* in_sizes, int n_in,
                              void* d_out, int out_size)
{
    // metadata order: W_D (f32), values (f32), layer_idx (i32), pos_idx (i32), feat_idx (i32)
    const float4* W    = (const float4*)d_in[0];
    const float*  vals = (const float*)d_in[1];
    const int*    lidx = (const int*)d_in[2];
    // pos_idx (d_in[3]) is unused by the reference computation
    const int*    fidx = (const int*)d_in[4];
    float4*       out  = (float4*)d_out;

    const int grid = NNZ / (WARPS_PER_BLOCK * ROWS_PER_WARP);   // 8192 blocks
    gather_scale_kernel<<<grid, THREADS>>>(W, vals, lidx, fidx, out);
}